// round 5
// baseline (speedup 1.0000x reference)
#include <cuda_runtime.h>
#include <math.h>

#define NN 50000
#define EE 1280000

// ---------------- device scratch (static, 16B-aligned for vector ops) ----------------
__device__ __align__(16) int   g_src[EE];
__device__ __align__(16) int   g_dst[EE];
__device__ __align__(16) float g_gate[EE];
__device__ __align__(16) float g_e1[EE];          // logit -> exp(gat)
__device__ __align__(16) float g_e2[EE];          // exp(cos) -> exp(fused*gate)
__device__ __align__(16) float g_H[NN * 64];      // x @ W
__device__ __align__(16) float g_xhat[NN * 64];   // normalized layer input
__device__ __align__(16) float g_h0[NN * 64];     // layer-0 output (layer-1 input)
__device__ __align__(16) float g_agg[NN * 64];    // aggregation buffer
__device__ __align__(16) float g_xres[NN * 64];   // residual branch
__device__ __align__(16) float g_tmp[NN * 64];
__device__ __align__(16) float g_ad[NN];          // H . att[:64]   (dst term)
__device__ __align__(16) float g_as[NN];          // H . att[64:]   (src term)
__device__ __align__(16) float g_maxg[NN];
__device__ __align__(16) float g_sumg[NN];
__device__ __align__(16) float g_sumc[NN];
__device__ __align__(16) float g_sumt[NN];
__device__ int g_is64;                            // edge_index dtype flag

// float atomic max via signed/unsigned int ordering trick (init = -inf)
__device__ __forceinline__ void atomicMaxF(float* a, float v) {
    if (v >= 0.f) atomicMax((int*)a, __float_as_int(v));
    else          atomicMin((unsigned int*)a, (unsigned int)__float_as_int(v));
}

// ---------------- dtype detection: int64 edge_index has zero high words ----------------
__global__ void detect_dtype(const int* __restrict__ ei_words) {
    if (threadIdx.x == 0 && blockIdx.x == 0) {
        int all_zero = 1;
        for (int i = 1; i < 2048; i += 2)
            if (ei_words[i] != 0) { all_zero = 0; break; }
        g_is64 = all_zero;
    }
}

// ---------------- setup: edges -> int32 (clamped), gate precompute ----------------
__global__ void edge_init(const int* __restrict__ ei, const float* __restrict__ w) {
    int e = blockIdx.x * blockDim.x + threadIdx.x;
    if (e >= EE) return;
    int s, d;
    if (g_is64) {                      // little-endian int64: low word at 2*idx
        s = ei[2 * e];
        d = ei[2 * (EE + e)];
    } else {
        s = ei[e];
        d = ei[EE + e];
    }
    g_src[e] = min(max(s, 0), NN - 1); // clamp: any parse error -> finite rel_err, not crash
    g_dst[e] = min(max(d, 0), NN - 1);
    float wc = fminf(w[e], 4.f);
    g_gate[e] = fminf(fmaxf(1.f - 0.25f * wc, 0.f), 1.f);
}

// ---------------- residual-branch GEMMs, warp-per-row, 2 cols/lane ----------------
// STAGE 0: relu(x @ rW1 + rb1) -> g_tmp     (X = kernel param)
// STAGE 1: g_tmp @ rW2 + rb2   -> g_xres
template <int STAGE>
__global__ void gemm_res(const float* __restrict__ Xin, const float* __restrict__ W,
                         const float* __restrict__ B) {
    int warp = (blockIdx.x * blockDim.x + threadIdx.x) >> 5;   // grid exact: warp < NN
    int lane = threadIdx.x & 31;
    const float* X = (STAGE == 0) ? Xin : g_tmp;
    float*       Y = (STAGE == 0) ? g_tmp : g_xres;
    float2 xa = ((const float2*)(X + (size_t)warp * 64))[lane];
    float a0 = 0.f, a1 = 0.f;
#pragma unroll
    for (int k = 0; k < 64; k += 2) {
        float x0 = __shfl_sync(0xffffffffu, xa.x, k >> 1);
        float x1 = __shfl_sync(0xffffffffu, xa.y, k >> 1);
        float2 w0 = ((const float2*)(W + k * 64))[lane];
        float2 w1 = ((const float2*)(W + (k + 1) * 64))[lane];
        a0 += x0 * w0.x + x1 * w1.x;
        a1 += x0 * w0.y + x1 * w1.y;
    }
    a0 += B[2 * lane]; a1 += B[2 * lane + 1];
    if (STAGE == 0) { a0 = fmaxf(a0, 0.f); a1 = fmaxf(a1, 0.f); }
    ((float2*)(Y + (size_t)warp * 64))[lane] = make_float2(a0, a1);
}

// ---------------- node prep: H = X@W, ad/as scalars, xhat ----------------
// LAYER 0 reads kernel param x; LAYER 1 reads g_h0.
template <int LAYER>
__global__ void node_prep(const float* __restrict__ Xin, const float* __restrict__ W,
                          const float* __restrict__ att) {
    int warp = (blockIdx.x * blockDim.x + threadIdx.x) >> 5;
    int lane = threadIdx.x & 31;
    const float* X = (LAYER == 0) ? Xin : g_h0;
    float2 xa = ((const float2*)(X + (size_t)warp * 64))[lane];
    float a0 = 0.f, a1 = 0.f;
#pragma unroll
    for (int k = 0; k < 64; k += 2) {
        float x0 = __shfl_sync(0xffffffffu, xa.x, k >> 1);
        float x1 = __shfl_sync(0xffffffffu, xa.y, k >> 1);
        float2 w0 = ((const float2*)(W + k * 64))[lane];
        float2 w1 = ((const float2*)(W + (k + 1) * 64))[lane];
        a0 += x0 * w0.x + x1 * w1.x;
        a1 += x0 * w0.y + x1 * w1.y;
    }
    ((float2*)(g_H + (size_t)warp * 64))[lane] = make_float2(a0, a1);
    float pa = a0 * att[2 * lane] + a1 * att[2 * lane + 1];
    float pb = a0 * att[64 + 2 * lane] + a1 * att[64 + 2 * lane + 1];
    float pn = xa.x * xa.x + xa.y * xa.y;
#pragma unroll
    for (int off = 16; off; off >>= 1) {
        pa += __shfl_down_sync(0xffffffffu, pa, off);
        pb += __shfl_down_sync(0xffffffffu, pb, off);
        pn += __shfl_down_sync(0xffffffffu, pn, off);
    }
    pn = __shfl_sync(0xffffffffu, pn, 0);
    float inv = 1.f / fmaxf(sqrtf(pn), 1e-8f);
    ((float2*)(g_xhat + (size_t)warp * 64))[lane] = make_float2(xa.x * inv, xa.y * inv);
    if (lane == 0) { g_ad[warp] = pa; g_as[warp] = pb; }
}

// ---------------- per-layer node accumulator init ----------------
__global__ void init_nodes() {
    int i = blockIdx.x * blockDim.x + threadIdx.x;   // grid exact: i < NN*64
    g_agg[i] = 0.f;
    if (i < NN) {
        g_maxg[i] = __int_as_float(0xff800000);      // -inf
        g_sumg[i] = 0.f; g_sumc[i] = 0.f; g_sumt[i] = 0.f;
    }
}

// ---------------- edge pass 1: cosine dot + GAT logit, sumc + maxg ----------------
// 16 lanes per edge (float4 per lane). Grid exact: EE*16 threads.
__global__ void edge_pass1() {
    int t = blockIdx.x * blockDim.x + threadIdx.x;
    int e = t >> 4, l = t & 15;
    int s = g_src[e], d = g_dst[e];
    float4 a = ((const float4*)g_xhat)[s * 16 + l];
    float4 b = ((const float4*)g_xhat)[d * 16 + l];
    float p = a.x * b.x + a.y * b.y + a.z * b.z + a.w * b.w;
    p += __shfl_down_sync(0xffffffffu, p, 8, 16);
    p += __shfl_down_sync(0xffffffffu, p, 4, 16);
    p += __shfl_down_sync(0xffffffffu, p, 2, 16);
    p += __shfl_down_sync(0xffffffffu, p, 1, 16);
    if (l == 0) {
        float lg = g_ad[d] + g_as[s];
        lg = lg >= 0.f ? lg : 0.2f * lg;             // leaky relu 0.2
        g_e1[e] = lg;
        float ec = __expf(p);                        // cos in [-1,1] -> no max shift needed
        g_e2[e] = ec;
        atomicAdd(&g_sumc[d], ec);
        atomicMaxF(&g_maxg[d], lg);
    }
}

// ---------------- edge pass 2: GAT softmax exp + sum ----------------
__global__ void edge_pass2() {
    int e = blockIdx.x * blockDim.x + threadIdx.x;
    if (e >= EE) return;
    int d = g_dst[e];
    float eg = __expf(g_e1[e] - g_maxg[d]);
    g_e1[e] = eg;
    atomicAdd(&g_sumg[d], eg);
}

// ---------------- edge pass 3: fuse alphas, gate, exp + sum ----------------
__global__ void edge_pass3(const float* __restrict__ beta) {
    int e = blockIdx.x * blockDim.x + threadIdx.x;
    if (e >= EE) return;
    int d = g_dst[e];
    float bb = 1.f / (1.f + __expf(-beta[0]));
    float ga = g_e1[e] / (g_sumg[d] + 1e-16f);
    float ca = g_e2[e] / (g_sumc[d] + 1e-16f);
    float tv = ((1.f - bb) * ga + bb * ca) * g_gate[e];   // in [0,1] -> no max shift
    float et = __expf(tv);
    g_e2[e] = et;
    atomicAdd(&g_sumt[d], et);
}

// ---------------- edge pass 4: weighted scatter-add of H[src] ----------------
__global__ void edge_pass4() {
    int t = blockIdx.x * blockDim.x + threadIdx.x;
    int e = t >> 4, l = t & 15;
    int s = g_src[e], d = g_dst[e];
    float fin = g_e2[e] / (g_sumt[d] + 1e-16f);
    float4 h = ((const float4*)g_H)[s * 16 + l];
    float* p = &g_agg[(size_t)d * 64 + l * 4];
    asm volatile("red.global.add.v4.f32 [%0], {%1,%2,%3,%4};"
                 :: "l"(p), "f"(h.x * fin), "f"(h.y * fin), "f"(h.z * fin), "f"(h.w * fin)
                 : "memory");
}

// ---------------- epilogues ----------------
__global__ void epilogue0(const float* __restrict__ B) {
    int i = blockIdx.x * blockDim.x + threadIdx.x;
    float v = g_agg[i] + B[i & 63];
    v = v > 0.f ? v : expm1f(v);      // elu inside _cosgat
    v = v > 0.f ? v : expm1f(v);      // inter-layer elu
    g_h0[i] = v;
}

__global__ void epilogue1(const float* __restrict__ B, float* __restrict__ out) {
    int i = blockIdx.x * blockDim.x + threadIdx.x;
    float v = g_agg[i] + B[i & 63];
    v = v > 0.f ? v : expm1f(v);
    out[i] = v + g_xres[i];
}

// ---------------- launch ----------------
extern "C" void kernel_launch(void* const* d_in, const int* in_sizes, int n_in,
                              void* d_out, int out_size) {
    const float* x     = (const float*)d_in[0];
    const int*   ei    = (const int*)d_in[1];    // dtype detected at runtime
    const float* ea    = (const float*)d_in[2];
    const float* W0    = (const float*)d_in[3];
    const float* att0  = (const float*)d_in[4];
    const float* beta0 = (const float*)d_in[5];
    const float* b0    = (const float*)d_in[6];
    const float* W1    = (const float*)d_in[7];
    const float* att1  = (const float*)d_in[8];
    const float* beta1 = (const float*)d_in[9];
    const float* b1    = (const float*)d_in[10];
    const float* rW1   = (const float*)d_in[11];
    const float* rb1   = (const float*)d_in[12];
    const float* rW2   = (const float*)d_in[13];
    const float* rb2   = (const float*)d_in[14];
    float* out = (float*)d_out;

    const int NODE_GRID  = NN / 8;        // 6250  (warp per row, 8 rows/block)
    const int ELEM_GRID  = NN * 64 / 256; // 12500
    const int EDGE_GRID  = EE / 256;      // 5000
    const int EDGE16     = EE / 16;       // 80000 (16 lanes/edge, 256 thr/block)

    detect_dtype<<<1, 32>>>(ei);
    edge_init<<<EDGE_GRID, 256>>>(ei, ea);

    // residual branch: relu(x@rW1+rb1)@rW2+rb2
    gemm_res<0><<<NODE_GRID, 256>>>(x, rW1, rb1);
    gemm_res<1><<<NODE_GRID, 256>>>(x, rW2, rb2);

    // -------- layer 0 --------
    init_nodes<<<ELEM_GRID, 256>>>();
    node_prep<0><<<NODE_GRID, 256>>>(x, W0, att0);
    edge_pass1<<<EDGE16, 256>>>();
    edge_pass2<<<EDGE_GRID, 256>>>();
    edge_pass3<<<EDGE_GRID, 256>>>(beta0);
    edge_pass4<<<EDGE16, 256>>>();
    epilogue0<<<ELEM_GRID, 256>>>(b0);

    // -------- layer 1 --------
    init_nodes<<<ELEM_GRID, 256>>>();
    node_prep<1><<<NODE_GRID, 256>>>(x, W1, att1);
    edge_pass1<<<EDGE16, 256>>>();
    edge_pass2<<<EDGE_GRID, 256>>>();
    edge_pass3<<<EDGE_GRID, 256>>>(beta1);
    edge_pass4<<<EDGE16, 256>>>();
    epilogue1<<<ELEM_GRID, 256>>>(b1, out);
}

// round 8
// speedup vs baseline: 1.3649x; 1.3649x over previous
#include <cuda_runtime.h>
#include <math.h>

#define NN 50000
#define EE 1280000

// ---------------- device scratch ----------------
__device__ __align__(16) int    g_src[EE];
__device__ __align__(16) int    g_dst[EE];
__device__ __align__(16) float  g_gate[EE];
__device__ __align__(16) int    g_csr_src[EE];
__device__ __align__(16) float  g_csr_gate[EE];
__device__ __align__(16) float2 g_ec[EE + 8];     // (raw logit, exp(cos)) per CSR edge
__device__ __align__(16) float  g_H[NN * 64];
__device__ __align__(16) float  g_xhat[NN * 64];
__device__ __align__(16) float  g_h0[NN * 64];
__device__ __align__(16) float  g_xres[NN * 64];
__device__ __align__(16) float  g_ad[NN];
__device__ __align__(16) float  g_as[NN];
__device__ int g_cnt[NN];
__device__ int g_rowptr[NN + 1];
__device__ int g_cur[NN];
__device__ int g_is64;

__device__ __forceinline__ float elu1(float v) { return v > 0.f ? v : expm1f(v); }

// ---------------- dtype detection ----------------
__global__ void detect_dtype(const int* __restrict__ ei_words) {
    if (threadIdx.x == 0 && blockIdx.x == 0) {
        int all_zero = 1;
        for (int i = 1; i < 2048; i += 2)
            if (ei_words[i] != 0) { all_zero = 0; break; }
        g_is64 = all_zero;
    }
}

__global__ void zero_cnt() {
    int i = blockIdx.x * blockDim.x + threadIdx.x;
    if (i < NN) g_cnt[i] = 0;
}

// ---------------- parse edges + gate + dst histogram ----------------
__global__ void edge_init(const int* __restrict__ ei, const float* __restrict__ w) {
    int e = blockIdx.x * blockDim.x + threadIdx.x;
    if (e >= EE) return;
    int s, d;
    if (g_is64) { s = ei[2 * e]; d = ei[2 * (EE + e)]; }
    else        { s = ei[e];     d = ei[EE + e]; }
    s = min(max(s, 0), NN - 1);
    d = min(max(d, 0), NN - 1);
    g_src[e] = s; g_dst[e] = d;
    float wc = fminf(w[e], 4.f);
    g_gate[e] = fminf(fmaxf(1.f - 0.25f * wc, 0.f), 1.f);
    atomicAdd(&g_cnt[d], 1);
}

// ---------------- single-block chunked scan -> rowptr + cur ----------------
__global__ void scan_kernel() {
    __shared__ int sm[1024];
    __shared__ int s_off;
    int t = threadIdx.x;
    if (t == 0) { s_off = 0; g_rowptr[0] = 0; }
    __syncthreads();
    for (int base = 0; base < NN; base += 1024) {
        int i = base + t;
        int v = (i < NN) ? g_cnt[i] : 0;
        sm[t] = v; __syncthreads();
        for (int o = 1; o < 1024; o <<= 1) {
            int add = (t >= o) ? sm[t - o] : 0;
            __syncthreads();
            sm[t] += add;
            __syncthreads();
        }
        int off = s_off;
        if (i < NN) {
            g_rowptr[i + 1] = off + sm[t];
            g_cur[i]        = off + sm[t] - v;
        }
        __syncthreads();
        if (t == 1023) s_off = off + sm[1023];
        __syncthreads();
    }
}

__global__ void scatter_edges() {
    int e = blockIdx.x * blockDim.x + threadIdx.x;
    if (e >= EE) return;
    int d = g_dst[e];
    int pos = atomicAdd(&g_cur[d], 1);
    g_csr_src[pos]  = g_src[e];
    g_csr_gate[pos] = g_gate[e];
}

// ---------------- fused residual MLP: relu(x@rW1+rb1)@rW2+rb2 -> g_xres ----------------
// 4 rows per warp: W streamed once per warp for 4 rows (4x less L1 traffic).
__global__ void gemm_res_fused(const float* __restrict__ X, const float* __restrict__ W1,
                               const float* __restrict__ B1, const float* __restrict__ W2,
                               const float* __restrict__ B2) {
    int warp = (blockIdx.x * blockDim.x + threadIdx.x) >> 5;
    int r0 = warp * 4;
    if (r0 >= NN) return;
    int lane = threadIdx.x & 31;
    float2 xa[4], t[4];
    float a0[4] = {0,0,0,0}, a1[4] = {0,0,0,0};
#pragma unroll
    for (int r = 0; r < 4; r++) xa[r] = ((const float2*)(X + (size_t)(r0 + r) * 64))[lane];
#pragma unroll
    for (int k = 0; k < 64; k += 2) {
        float2 w0 = ((const float2*)(W1 + k * 64))[lane];
        float2 w1 = ((const float2*)(W1 + (k + 1) * 64))[lane];
#pragma unroll
        for (int r = 0; r < 4; r++) {
            float x0 = __shfl_sync(0xffffffffu, xa[r].x, k >> 1);
            float x1 = __shfl_sync(0xffffffffu, xa[r].y, k >> 1);
            a0[r] += x0 * w0.x + x1 * w1.x;
            a1[r] += x0 * w0.y + x1 * w1.y;
        }
    }
    float bb0 = B1[2 * lane], bb1 = B1[2 * lane + 1];
#pragma unroll
    for (int r = 0; r < 4; r++) {
        t[r].x = fmaxf(a0[r] + bb0, 0.f);
        t[r].y = fmaxf(a1[r] + bb1, 0.f);
        a0[r] = 0.f; a1[r] = 0.f;
    }
#pragma unroll
    for (int k = 0; k < 64; k += 2) {
        float2 w0 = ((const float2*)(W2 + k * 64))[lane];
        float2 w1 = ((const float2*)(W2 + (k + 1) * 64))[lane];
#pragma unroll
        for (int r = 0; r < 4; r++) {
            float x0 = __shfl_sync(0xffffffffu, t[r].x, k >> 1);
            float x1 = __shfl_sync(0xffffffffu, t[r].y, k >> 1);
            a0[r] += x0 * w0.x + x1 * w1.x;
            a1[r] += x0 * w0.y + x1 * w1.y;
        }
    }
    float c0 = B2[2 * lane], c1 = B2[2 * lane + 1];
#pragma unroll
    for (int r = 0; r < 4; r++)
        ((float2*)(g_xres + (size_t)(r0 + r) * 64))[lane] = make_float2(a0[r] + c0, a1[r] + c1);
}

// ---------------- node prep: H=X@W, ad/as, xhat  (4 rows/warp) ----------------
template <int LAYER>
__global__ void node_prep(const float* __restrict__ Xin, const float* __restrict__ W,
                          const float* __restrict__ att) {
    int warp = (blockIdx.x * blockDim.x + threadIdx.x) >> 5;
    int r0 = warp * 4;
    if (r0 >= NN) return;
    int lane = threadIdx.x & 31;
    const float* X = (LAYER == 0) ? Xin : g_h0;
    float2 xa[4];
    float a0[4] = {0,0,0,0}, a1[4] = {0,0,0,0};
#pragma unroll
    for (int r = 0; r < 4; r++) xa[r] = ((const float2*)(X + (size_t)(r0 + r) * 64))[lane];
#pragma unroll
    for (int k = 0; k < 64; k += 2) {
        float2 w0 = ((const float2*)(W + k * 64))[lane];
        float2 w1 = ((const float2*)(W + (k + 1) * 64))[lane];
#pragma unroll
        for (int r = 0; r < 4; r++) {
            float x0 = __shfl_sync(0xffffffffu, xa[r].x, k >> 1);
            float x1 = __shfl_sync(0xffffffffu, xa[r].y, k >> 1);
            a0[r] += x0 * w0.x + x1 * w1.x;
            a1[r] += x0 * w0.y + x1 * w1.y;
        }
    }
    float at0 = att[2 * lane], at1 = att[2 * lane + 1];
    float at2 = att[64 + 2 * lane], at3 = att[65 + 2 * lane];
#pragma unroll
    for (int r = 0; r < 4; r++) {
        ((float2*)(g_H + (size_t)(r0 + r) * 64))[lane] = make_float2(a0[r], a1[r]);
        float pa = a0[r] * at0 + a1[r] * at1;
        float pb = a0[r] * at2 + a1[r] * at3;
        float pn = xa[r].x * xa[r].x + xa[r].y * xa[r].y;
#pragma unroll
        for (int o = 16; o; o >>= 1) {
            pa += __shfl_xor_sync(0xffffffffu, pa, o);
            pb += __shfl_xor_sync(0xffffffffu, pb, o);
            pn += __shfl_xor_sync(0xffffffffu, pn, o);
        }
        float inv = 1.f / fmaxf(sqrtf(pn), 1e-8f);
        ((float2*)(g_xhat + (size_t)(r0 + r) * 64))[lane] =
            make_float2(xa[r].x * inv, xa[r].y * inv);
        if (lane == 0) { g_ad[r0 + r] = pa; g_as[r0 + r] = pb; }
    }
}

// ---------------- fused edge engine: warp per node, no atomics ----------------
// Pass A: cos + logit per edge (8 lanes/edge, 4 edges/iter), online GAT softmax stats.
// Pass C: fused alpha, gate, exp; unnormalized aggregate; divide at end.
template <int LAYER>
__global__ void edge_fused(const float* __restrict__ beta, const float* __restrict__ B,
                           float* __restrict__ outp) {
    int n = (blockIdx.x * blockDim.x + threadIdx.x) >> 5;
    if (n >= NN) return;
    int lane = threadIdx.x & 31;
    int p = lane & 7;          // float4 slot within 8-lane group
    int grp = lane >> 3;       // edge group 0..3

    const float* xrow = g_xhat + (size_t)n * 64;
    float4 xq0 = *((const float4*)(xrow + p * 4));
    float4 xq1 = *((const float4*)(xrow + 32 + p * 4));
    float ad = g_ad[n];
    int beg = g_rowptr[n], end = g_rowptr[n + 1];
    float bb = 1.f / (1.f + __expf(-beta[0]));

    const float NINF = __int_as_float(0xff800000);
    float m = NINF, sg = 0.f, sc = 0.f;

    for (int j0 = beg; j0 < end; j0 += 4) {
        int idx = j0 + grp;
        int s = (idx < end) ? g_csr_src[idx] : 0;
        const float* ar = g_xhat + (size_t)s * 64;
        float4 q0 = *((const float4*)(ar + p * 4));
        float4 q1 = *((const float4*)(ar + 32 + p * 4));
        float d = xq0.x*q0.x + xq0.y*q0.y + xq0.z*q0.z + xq0.w*q0.w
                + xq1.x*q1.x + xq1.y*q1.y + xq1.z*q1.z + xq1.w*q1.w;
        d += __shfl_xor_sync(0xffffffffu, d, 4, 8);
        d += __shfl_xor_sync(0xffffffffu, d, 2, 8);
        d += __shfl_xor_sync(0xffffffffu, d, 1, 8);
        // edge i's dot lives in lanes 8i..8i+7; lane i (<4) collects edge i
        float dsel = __shfl_sync(0xffffffffu, d, (lane * 8) & 31);
        int   ssel = __shfl_sync(0xffffffffu, s, (lane * 8) & 31);
        int cnt = min(4, end - j0);
        if (lane < cnt) {
            float lg = ad + g_as[ssel];
            lg = fmaxf(lg, 0.2f * lg);                   // leaky relu
            float ecv = __expf(dsel);                    // cos in [-1,1]: no shift
            g_ec[j0 + lane] = make_float2(lg, ecv);
            float mo = m;
            m = fmaxf(m, lg);
            sg = sg * __expf(mo - m) + __expf(lg - m);   // online softmax
            sc += ecv;
        }
    }
    // combine online stats across lanes 0..3
#pragma unroll
    for (int o = 1; o <= 2; o <<= 1) {
        float m2  = __shfl_xor_sync(0xffffffffu, m, o, 4);
        float sg2 = __shfl_xor_sync(0xffffffffu, sg, o, 4);
        float sc2 = __shfl_xor_sync(0xffffffffu, sc, o, 4);
        float mm = fmaxf(m, m2);
        float t1 = (sg  > 0.f) ? sg  * __expf(m  - mm) : 0.f;
        float t2 = (sg2 > 0.f) ? sg2 * __expf(m2 - mm) : 0.f;
        m = mm; sg = t1 + t2; sc += sc2;
    }
    m  = __shfl_sync(0xffffffffu, m, 0);
    sg = __shfl_sync(0xffffffffu, sg, 0);
    sc = __shfl_sync(0xffffffffu, sc, 0);
    float wg = (1.f - bb) / (sg + 1e-16f);
    float wc = bb / (sc + 1e-16f);

    // Pass C
    float4 acc0 = make_float4(0,0,0,0), acc1 = make_float4(0,0,0,0);
    float st = 0.f;
    for (int j0 = beg; j0 < end; j0 += 4) {
        int idx = j0 + grp;
        int s = (idx < end) ? g_csr_src[idx] : 0;
        int cnt = min(4, end - j0);
        float et = 0.f;
        if (lane < cnt) {
            float2 le = g_ec[j0 + lane];
            float eg = __expf(le.x - m);
            float tv = (eg * wg + le.y * wc) * g_csr_gate[j0 + lane];  // in [0,1]
            et = __expf(tv);
            st += et;
        }
        float etg = __shfl_sync(0xffffffffu, et, grp);   // et for my group's edge
        const float* hr = g_H + (size_t)s * 64;
        float4 h0 = *((const float4*)(hr + p * 4));
        float4 h1 = *((const float4*)(hr + 32 + p * 4));
        acc0.x += etg * h0.x; acc0.y += etg * h0.y; acc0.z += etg * h0.z; acc0.w += etg * h0.w;
        acc1.x += etg * h1.x; acc1.y += etg * h1.y; acc1.z += etg * h1.z; acc1.w += etg * h1.w;
    }
    st += __shfl_xor_sync(0xffffffffu, st, 1, 4);
    st += __shfl_xor_sync(0xffffffffu, st, 2, 4);
    st  = __shfl_sync(0xffffffffu, st, 0);
#pragma unroll
    for (int o = 8; o <= 16; o <<= 1) {
        acc0.x += __shfl_xor_sync(0xffffffffu, acc0.x, o);
        acc0.y += __shfl_xor_sync(0xffffffffu, acc0.y, o);
        acc0.z += __shfl_xor_sync(0xffffffffu, acc0.z, o);
        acc0.w += __shfl_xor_sync(0xffffffffu, acc0.w, o);
        acc1.x += __shfl_xor_sync(0xffffffffu, acc1.x, o);
        acc1.y += __shfl_xor_sync(0xffffffffu, acc1.y, o);
        acc1.z += __shfl_xor_sync(0xffffffffu, acc1.z, o);
        acc1.w += __shfl_xor_sync(0xffffffffu, acc1.w, o);
    }
    float inv = 1.f / (st + 1e-16f);
    if (lane < 8) {
        float4 b0 = *((const float4*)(B + lane * 4));
        float4 b1 = *((const float4*)(B + 32 + lane * 4));
        float4 o0, o1;
        o0.x = acc0.x * inv + b0.x; o0.y = acc0.y * inv + b0.y;
        o0.z = acc0.z * inv + b0.z; o0.w = acc0.w * inv + b0.w;
        o1.x = acc1.x * inv + b1.x; o1.y = acc1.y * inv + b1.y;
        o1.z = acc1.z * inv + b1.z; o1.w = acc1.w * inv + b1.w;
        if (LAYER == 0) {
            o0.x = elu1(elu1(o0.x)); o0.y = elu1(elu1(o0.y));
            o0.z = elu1(elu1(o0.z)); o0.w = elu1(elu1(o0.w));
            o1.x = elu1(elu1(o1.x)); o1.y = elu1(elu1(o1.y));
            o1.z = elu1(elu1(o1.z)); o1.w = elu1(elu1(o1.w));
            *((float4*)(g_h0 + (size_t)n * 64 + lane * 4)) = o0;
            *((float4*)(g_h0 + (size_t)n * 64 + 32 + lane * 4)) = o1;
        } else {
            float4 r0 = *((const float4*)(g_xres + (size_t)n * 64 + lane * 4));
            float4 r1 = *((const float4*)(g_xres + (size_t)n * 64 + 32 + lane * 4));
            o0.x = elu1(o0.x) + r0.x; o0.y = elu1(o0.y) + r0.y;
            o0.z = elu1(o0.z) + r0.z; o0.w = elu1(o0.w) + r0.w;
            o1.x = elu1(o1.x) + r1.x; o1.y = elu1(o1.y) + r1.y;
            o1.z = elu1(o1.z) + r1.z; o1.w = elu1(o1.w) + r1.w;
            *((float4*)(outp + (size_t)n * 64 + lane * 4)) = o0;
            *((float4*)(outp + (size_t)n * 64 + 32 + lane * 4)) = o1;
        }
    }
}

// ---------------- launch ----------------
extern "C" void kernel_launch(void* const* d_in, const int* in_sizes, int n_in,
                              void* d_out, int out_size) {
    const float* x     = (const float*)d_in[0];
    const int*   ei    = (const int*)d_in[1];
    const float* ea    = (const float*)d_in[2];
    const float* W0    = (const float*)d_in[3];
    const float* att0  = (const float*)d_in[4];
    const float* beta0 = (const float*)d_in[5];
    const float* b0    = (const float*)d_in[6];
    const float* W1    = (const float*)d_in[7];
    const float* att1  = (const float*)d_in[8];
    const float* beta1 = (const float*)d_in[9];
    const float* b1    = (const float*)d_in[10];
    const float* rW1   = (const float*)d_in[11];
    const float* rb1   = (const float*)d_in[12];
    const float* rW2   = (const float*)d_in[13];
    const float* rb2   = (const float*)d_in[14];
    float* out = (float*)d_out;

    const int EDGE_GRID = EE / 256;                 // 5000
    const int CNT_GRID  = (NN + 255) / 256;         // 196
    const int PREP_GRID = (NN / 4 + 7) / 8;         // 1563 (4 rows/warp, 8 warps/blk)
    const int EDGEF_GRID = NN / 8;                  // 6250 (warp per node)

    detect_dtype<<<1, 32>>>(ei);
    zero_cnt<<<CNT_GRID, 256>>>();
    edge_init<<<EDGE_GRID, 256>>>(ei, ea);
    scan_kernel<<<1, 1024>>>();
    scatter_edges<<<EDGE_GRID, 256>>>();

    gemm_res_fused<<<PREP_GRID, 256>>>(x, rW1, rb1, rW2, rb2);

    node_prep<0><<<PREP_GRID, 256>>>(x, W0, att0);
    edge_fused<0><<<EDGEF_GRID, 256>>>(beta0, b0, out);

    node_prep<1><<<PREP_GRID, 256>>>(x, W1, att1);
    edge_fused<1><<<EDGEF_GRID, 256>>>(beta1, b1, out);
}

// round 10
// speedup vs baseline: 1.6091x; 1.1789x over previous
#include <cuda_runtime.h>
#include <math.h>

#define NN 50000
#define EE 1280000
#define NBLK 196            // ceil(NN/256)

// ---------------- device scratch ----------------
__device__ __align__(16) int    g_csr_src[EE];
__device__ __align__(16) float  g_csr_gate[EE];
__device__ __align__(16) float2 g_ec[EE + 8];     // (raw logit, exp(cos)) per CSR edge
__device__ __align__(16) float  g_H[NN * 64];
__device__ __align__(16) float  g_xhat[NN * 64];
__device__ __align__(16) float  g_h0[NN * 64];
__device__ __align__(16) float  g_xres[NN * 64];
__device__ __align__(16) float  g_ad[NN];
__device__ __align__(16) float  g_as[NN];
__device__ int g_cnt[NN];
__device__ int g_rowptr[NN + 1];
__device__ int g_cur[NN];
__device__ int g_bsum[NBLK + 32];
__device__ int g_boff[NBLK + 32];
__device__ int g_is64;

__device__ __forceinline__ float elu1(float v) { return v > 0.f ? v : expm1f(v); }

// ---------------- dtype detection ----------------
__global__ void detect_dtype(const int* __restrict__ ei_words) {
    if (threadIdx.x == 0 && blockIdx.x == 0) {
        int all_zero = 1;
        for (int i = 1; i < 2048; i += 2)
            if (ei_words[i] != 0) { all_zero = 0; break; }
        g_is64 = all_zero;
    }
}

__global__ void zero_cnt() {
    int i = blockIdx.x * blockDim.x + threadIdx.x;
    if (i < NN) g_cnt[i] = 0;
}

__device__ __forceinline__ int parse_dst(const int* ei, int e) {
    int d = g_is64 ? ei[2 * (EE + e)] : ei[EE + e];
    return min(max(d, 0), NN - 1);
}
__device__ __forceinline__ int parse_src(const int* ei, int e) {
    int s = g_is64 ? ei[2 * e] : ei[e];
    return min(max(s, 0), NN - 1);
}

// ---------------- histogram of dst ----------------
__global__ void edge_hist(const int* __restrict__ ei) {
    int e = blockIdx.x * blockDim.x + threadIdx.x;
    if (e >= EE) return;
    atomicAdd(&g_cnt[parse_dst(ei, e)], 1);
}

// ---------------- multi-block exclusive scan of g_cnt -> rowptr/cur ----------------
// Phase A: per-block sum of 256 counts
__global__ void scan_reduce() {
    int i = blockIdx.x * blockDim.x + threadIdx.x;
    int v = (i < NN) ? g_cnt[i] : 0;
#pragma unroll
    for (int o = 16; o; o >>= 1) v += __shfl_xor_sync(0xffffffffu, v, o);
    __shared__ int sm[8];
    if ((threadIdx.x & 31) == 0) sm[threadIdx.x >> 5] = v;
    __syncthreads();
    if (threadIdx.x == 0) {
        int t = 0;
#pragma unroll
        for (int w = 0; w < 8; w++) t += sm[w];
        g_bsum[blockIdx.x] = t;
    }
}

// Phase B: one block scans NBLK partials (exclusive)
__global__ void scan_partials() {
    int t = threadIdx.x;                       // 256 threads
    int v = (t < NBLK) ? g_bsum[t] : 0;
    __shared__ int sm[256];
    sm[t] = v; __syncthreads();
    int acc = v;
#pragma unroll
    for (int o = 1; o < 256; o <<= 1) {
        int add = (t >= o) ? sm[t - o] : 0;
        __syncthreads();
        acc += add; sm[t] = acc;
        __syncthreads();
    }
    if (t < NBLK) g_boff[t] = acc - v;          // exclusive
}

// Phase C: per-block local scan + global offset -> rowptr, cur
__global__ void scan_apply() {
    int t = threadIdx.x;
    int i = blockIdx.x * 256 + t;
    int v = (i < NN) ? g_cnt[i] : 0;
    __shared__ int sm[256];
    sm[t] = v; __syncthreads();
    int acc = v;
#pragma unroll
    for (int o = 1; o < 256; o <<= 1) {
        int add = (t >= o) ? sm[t - o] : 0;
        __syncthreads();
        acc += add; sm[t] = acc;
        __syncthreads();
    }
    int off = g_boff[blockIdx.x];
    if (i < NN) {
        g_rowptr[i + 1] = off + acc;
        g_cur[i]        = off + acc - v;
    }
    if (i == 0) g_rowptr[0] = 0;
}

// ---------------- scatter edges into CSR (parses inputs directly) ----------------
__global__ void scatter_edges(const int* __restrict__ ei, const float* __restrict__ w) {
    int e = blockIdx.x * blockDim.x + threadIdx.x;
    if (e >= EE) return;
    int d = parse_dst(ei, e);
    int pos = atomicAdd(&g_cur[d], 1);
    g_csr_src[pos] = parse_src(ei, e);
    float wc = fminf(w[e], 4.f);
    g_csr_gate[pos] = fminf(fmaxf(1.f - 0.25f * wc, 0.f), 1.f);
}

// ---------------- fused residual MLP: relu(x@rW1+rb1)@rW2+rb2 -> g_xres ----------------
__global__ void gemm_res_fused(const float* __restrict__ X, const float* __restrict__ W1,
                               const float* __restrict__ B1, const float* __restrict__ W2,
                               const float* __restrict__ B2) {
    int warp = (blockIdx.x * blockDim.x + threadIdx.x) >> 5;
    int r0 = warp * 4;
    if (r0 >= NN) return;
    int lane = threadIdx.x & 31;
    float2 xa[4], t[4];
    float a0[4] = {0,0,0,0}, a1[4] = {0,0,0,0};
#pragma unroll
    for (int r = 0; r < 4; r++) xa[r] = ((const float2*)(X + (size_t)(r0 + r) * 64))[lane];
#pragma unroll
    for (int k = 0; k < 64; k += 2) {
        float2 w0 = ((const float2*)(W1 + k * 64))[lane];
        float2 w1 = ((const float2*)(W1 + (k + 1) * 64))[lane];
#pragma unroll
        for (int r = 0; r < 4; r++) {
            float x0 = __shfl_sync(0xffffffffu, xa[r].x, k >> 1);
            float x1 = __shfl_sync(0xffffffffu, xa[r].y, k >> 1);
            a0[r] += x0 * w0.x + x1 * w1.x;
            a1[r] += x0 * w0.y + x1 * w1.y;
        }
    }
    float bb0 = B1[2 * lane], bb1 = B1[2 * lane + 1];
#pragma unroll
    for (int r = 0; r < 4; r++) {
        t[r].x = fmaxf(a0[r] + bb0, 0.f);
        t[r].y = fmaxf(a1[r] + bb1, 0.f);
        a0[r] = 0.f; a1[r] = 0.f;
    }
#pragma unroll
    for (int k = 0; k < 64; k += 2) {
        float2 w0 = ((const float2*)(W2 + k * 64))[lane];
        float2 w1 = ((const float2*)(W2 + (k + 1) * 64))[lane];
#pragma unroll
        for (int r = 0; r < 4; r++) {
            float x0 = __shfl_sync(0xffffffffu, t[r].x, k >> 1);
            float x1 = __shfl_sync(0xffffffffu, t[r].y, k >> 1);
            a0[r] += x0 * w0.x + x1 * w1.x;
            a1[r] += x0 * w0.y + x1 * w1.y;
        }
    }
    float c0 = B2[2 * lane], c1 = B2[2 * lane + 1];
#pragma unroll
    for (int r = 0; r < 4; r++)
        ((float2*)(g_xres + (size_t)(r0 + r) * 64))[lane] = make_float2(a0[r] + c0, a1[r] + c1);
}

// ---------------- node prep: H=X@W, ad/as, xhat  (4 rows/warp) ----------------
template <int LAYER>
__global__ void node_prep(const float* __restrict__ Xin, const float* __restrict__ W,
                          const float* __restrict__ att) {
    int warp = (blockIdx.x * blockDim.x + threadIdx.x) >> 5;
    int r0 = warp * 4;
    if (r0 >= NN) return;
    int lane = threadIdx.x & 31;
    const float* X = (LAYER == 0) ? Xin : g_h0;
    float2 xa[4];
    float a0[4] = {0,0,0,0}, a1[4] = {0,0,0,0};
#pragma unroll
    for (int r = 0; r < 4; r++) xa[r] = ((const float2*)(X + (size_t)(r0 + r) * 64))[lane];
#pragma unroll
    for (int k = 0; k < 64; k += 2) {
        float2 w0 = ((const float2*)(W + k * 64))[lane];
        float2 w1 = ((const float2*)(W + (k + 1) * 64))[lane];
#pragma unroll
        for (int r = 0; r < 4; r++) {
            float x0 = __shfl_sync(0xffffffffu, xa[r].x, k >> 1);
            float x1 = __shfl_sync(0xffffffffu, xa[r].y, k >> 1);
            a0[r] += x0 * w0.x + x1 * w1.x;
            a1[r] += x0 * w0.y + x1 * w1.y;
        }
    }
    float at0 = att[2 * lane], at1 = att[2 * lane + 1];
    float at2 = att[64 + 2 * lane], at3 = att[65 + 2 * lane];
#pragma unroll
    for (int r = 0; r < 4; r++) {
        ((float2*)(g_H + (size_t)(r0 + r) * 64))[lane] = make_float2(a0[r], a1[r]);
        float pa = a0[r] * at0 + a1[r] * at1;
        float pb = a0[r] * at2 + a1[r] * at3;
        float pn = xa[r].x * xa[r].x + xa[r].y * xa[r].y;
#pragma unroll
        for (int o = 16; o; o >>= 1) {
            pa += __shfl_xor_sync(0xffffffffu, pa, o);
            pb += __shfl_xor_sync(0xffffffffu, pb, o);
            pn += __shfl_xor_sync(0xffffffffu, pn, o);
        }
        float inv = 1.f / fmaxf(sqrtf(pn), 1e-8f);
        ((float2*)(g_xhat + (size_t)(r0 + r) * 64))[lane] =
            make_float2(xa[r].x * inv, xa[r].y * inv);
        if (lane == 0) { g_ad[r0 + r] = pa; g_as[r0 + r] = pb; }
    }
}

// ---------------- fused edge engine: warp per node, no atomics ----------------
template <int LAYER>
__global__ void edge_fused(const float* __restrict__ beta, const float* __restrict__ B,
                           float* __restrict__ outp) {
    int n = (blockIdx.x * blockDim.x + threadIdx.x) >> 5;
    if (n >= NN) return;
    int lane = threadIdx.x & 31;
    int p = lane & 7;          // float4 slot within 8-lane group
    int grp = lane >> 3;       // edge group 0..3

    const float* xrow = g_xhat + (size_t)n * 64;
    float4 xq0 = *((const float4*)(xrow + p * 4));
    float4 xq1 = *((const float4*)(xrow + 32 + p * 4));
    float ad = g_ad[n];
    int beg = g_rowptr[n], end = g_rowptr[n + 1];
    float bb = 1.f / (1.f + __expf(-beta[0]));

    const float NINF = __int_as_float(0xff800000);
    float m = NINF, sg = 0.f, sc = 0.f;

    for (int j0 = beg; j0 < end; j0 += 4) {
        int idx = j0 + grp;
        int s = (idx < end) ? g_csr_src[idx] : 0;
        const float* ar = g_xhat + (size_t)s * 64;
        float4 q0 = *((const float4*)(ar + p * 4));
        float4 q1 = *((const float4*)(ar + 32 + p * 4));
        float d = xq0.x*q0.x + xq0.y*q0.y + xq0.z*q0.z + xq0.w*q0.w
                + xq1.x*q1.x + xq1.y*q1.y + xq1.z*q1.z + xq1.w*q1.w;
        d += __shfl_xor_sync(0xffffffffu, d, 4, 8);
        d += __shfl_xor_sync(0xffffffffu, d, 2, 8);
        d += __shfl_xor_sync(0xffffffffu, d, 1, 8);
        float dsel = __shfl_sync(0xffffffffu, d, (lane * 8) & 31);
        int   ssel = __shfl_sync(0xffffffffu, s, (lane * 8) & 31);
        int cnt = min(4, end - j0);
        if (lane < cnt) {
            float lg = ad + g_as[ssel];
            lg = fmaxf(lg, 0.2f * lg);                   // leaky relu
            float ecv = __expf(dsel);                    // cos in [-1,1]: no shift
            g_ec[j0 + lane] = make_float2(lg, ecv);
            float mo = m;
            m = fmaxf(m, lg);
            sg = sg * __expf(mo - m) + __expf(lg - m);   // online softmax
            sc += ecv;
        }
    }
#pragma unroll
    for (int o = 1; o <= 2; o <<= 1) {
        float m2  = __shfl_xor_sync(0xffffffffu, m, o, 4);
        float sg2 = __shfl_xor_sync(0xffffffffu, sg, o, 4);
        float sc2 = __shfl_xor_sync(0xffffffffu, sc, o, 4);
        float mm = fmaxf(m, m2);
        float t1 = (sg  > 0.f) ? sg  * __expf(m  - mm) : 0.f;
        float t2 = (sg2 > 0.f) ? sg2 * __expf(m2 - mm) : 0.f;
        m = mm; sg = t1 + t2; sc += sc2;
    }
    m  = __shfl_sync(0xffffffffu, m, 0);
    sg = __shfl_sync(0xffffffffu, sg, 0);
    sc = __shfl_sync(0xffffffffu, sc, 0);
    float wg = (1.f - bb) / (sg + 1e-16f);
    float wc = bb / (sc + 1e-16f);

    // Pass C
    float4 acc0 = make_float4(0,0,0,0), acc1 = make_float4(0,0,0,0);
    float st = 0.f;
    for (int j0 = beg; j0 < end; j0 += 4) {
        int idx = j0 + grp;
        int s = (idx < end) ? g_csr_src[idx] : 0;
        int cnt = min(4, end - j0);
        float et = 0.f;
        if (lane < cnt) {
            float2 le = g_ec[j0 + lane];
            float eg = __expf(le.x - m);
            float tv = (eg * wg + le.y * wc) * g_csr_gate[j0 + lane];  // in [0,1]
            et = __expf(tv);
            st += et;
        }
        float etg = __shfl_sync(0xffffffffu, et, grp);
        const float* hr = g_H + (size_t)s * 64;
        float4 h0 = *((const float4*)(hr + p * 4));
        float4 h1 = *((const float4*)(hr + 32 + p * 4));
        acc0.x += etg * h0.x; acc0.y += etg * h0.y; acc0.z += etg * h0.z; acc0.w += etg * h0.w;
        acc1.x += etg * h1.x; acc1.y += etg * h1.y; acc1.z += etg * h1.z; acc1.w += etg * h1.w;
    }
    st += __shfl_xor_sync(0xffffffffu, st, 1, 4);
    st += __shfl_xor_sync(0xffffffffu, st, 2, 4);
    st  = __shfl_sync(0xffffffffu, st, 0);
#pragma unroll
    for (int o = 8; o <= 16; o <<= 1) {
        acc0.x += __shfl_xor_sync(0xffffffffu, acc0.x, o);
        acc0.y += __shfl_xor_sync(0xffffffffu, acc0.y, o);
        acc0.z += __shfl_xor_sync(0xffffffffu, acc0.z, o);
        acc0.w += __shfl_xor_sync(0xffffffffu, acc0.w, o);
        acc1.x += __shfl_xor_sync(0xffffffffu, acc1.x, o);
        acc1.y += __shfl_xor_sync(0xffffffffu, acc1.y, o);
        acc1.z += __shfl_xor_sync(0xffffffffu, acc1.z, o);
        acc1.w += __shfl_xor_sync(0xffffffffu, acc1.w, o);
    }
    float inv = 1.f / (st + 1e-16f);
    if (lane < 8) {
        float4 b0 = *((const float4*)(B + lane * 4));
        float4 b1 = *((const float4*)(B + 32 + lane * 4));
        float4 o0, o1;
        o0.x = acc0.x * inv + b0.x; o0.y = acc0.y * inv + b0.y;
        o0.z = acc0.z * inv + b0.z; o0.w = acc0.w * inv + b0.w;
        o1.x = acc1.x * inv + b1.x; o1.y = acc1.y * inv + b1.y;
        o1.z = acc1.z * inv + b1.z; o1.w = acc1.w * inv + b1.w;
        if (LAYER == 0) {
            o0.x = elu1(elu1(o0.x)); o0.y = elu1(elu1(o0.y));
            o0.z = elu1(elu1(o0.z)); o0.w = elu1(elu1(o0.w));
            o1.x = elu1(elu1(o1.x)); o1.y = elu1(elu1(o1.y));
            o1.z = elu1(elu1(o1.z)); o1.w = elu1(elu1(o1.w));
            *((float4*)(g_h0 + (size_t)n * 64 + lane * 4)) = o0;
            *((float4*)(g_h0 + (size_t)n * 64 + 32 + lane * 4)) = o1;
        } else {
            float4 r0 = *((const float4*)(g_xres + (size_t)n * 64 + lane * 4));
            float4 r1 = *((const float4*)(g_xres + (size_t)n * 64 + 32 + lane * 4));
            o0.x = elu1(o0.x) + r0.x; o0.y = elu1(o0.y) + r0.y;
            o0.z = elu1(o0.z) + r0.z; o0.w = elu1(o0.w) + r0.w;
            o1.x = elu1(o1.x) + r1.x; o1.y = elu1(o1.y) + r1.y;
            o1.z = elu1(o1.z) + r1.z; o1.w = elu1(o1.w) + r1.w;
            *((float4*)(outp + (size_t)n * 64 + lane * 4)) = o0;
            *((float4*)(outp + (size_t)n * 64 + 32 + lane * 4)) = o1;
        }
    }
}

// ---------------- launch ----------------
extern "C" void kernel_launch(void* const* d_in, const int* in_sizes, int n_in,
                              void* d_out, int out_size) {
    const float* x     = (const float*)d_in[0];
    const int*   ei    = (const int*)d_in[1];
    const float* ea    = (const float*)d_in[2];
    const float* W0    = (const float*)d_in[3];
    const float* att0  = (const float*)d_in[4];
    const float* beta0 = (const float*)d_in[5];
    const float* b0    = (const float*)d_in[6];
    const float* W1    = (const float*)d_in[7];
    const float* att1  = (const float*)d_in[8];
    const float* beta1 = (const float*)d_in[9];
    const float* b1    = (const float*)d_in[10];
    const float* rW1   = (const float*)d_in[11];
    const float* rb1   = (const float*)d_in[12];
    const float* rW2   = (const float*)d_in[13];
    const float* rb2   = (const float*)d_in[14];
    float* out = (float*)d_out;

    const int EDGE_GRID  = EE / 256;                 // 5000
    const int PREP_GRID  = (NN / 4 + 7) / 8;         // 1563 (4 rows/warp, 8 warps/blk)
    const int EDGEF_GRID = NN / 8;                   // 6250 (warp per node)

    detect_dtype<<<1, 32>>>(ei);
    zero_cnt<<<NBLK, 256>>>();
    edge_hist<<<EDGE_GRID, 256>>>(ei);
    scan_reduce<<<NBLK, 256>>>();
    scan_partials<<<1, 256>>>();
    scan_apply<<<NBLK, 256>>>();
    scatter_edges<<<EDGE_GRID, 256>>>(ei, ea);

    gemm_res_fused<<<PREP_GRID, 256>>>(x, rW1, rb1, rW2, rb2);

    node_prep<0><<<PREP_GRID, 256>>>(x, W0, att0);
    edge_fused<0><<<EDGEF_GRID, 256>>>(beta0, b0, out);

    node_prep<1><<<PREP_GRID, 256>>>(x, W1, att1);
    edge_fused<1><<<EDGEF_GRID, 256>>>(beta1, b1, out);
}

// round 14
// speedup vs baseline: 1.7938x; 1.1148x over previous
#include <cuda_runtime.h>
#include <cuda_fp16.h>
#include <math.h>

#define NN 50000
#define EE 1280000
#define NBLK 196            // ceil(NN/256)

// ---------------- device scratch ----------------
__device__ __align__(16) int    g_csr_src[EE];
__device__ __align__(16) float  g_csr_gate[EE];
__device__ __align__(16) float2 g_ec[EE + 8];       // (raw logit, exp(cos)) per CSR edge
__device__ __align__(16) __half g_Hh[NN * 64];      // H = X@W   (fp16 for gather BW)
__device__ __align__(16) __half g_xh[NN * 64];      // xhat      (fp16 for gather BW)
__device__ __align__(16) float  g_h0[NN * 64];
__device__ __align__(16) float  g_xres[NN * 64];
__device__ __align__(16) float  g_ad[NN];
__device__ __align__(16) float  g_as[NN];
__device__ int g_cnt[NN];
__device__ int g_rowptr[NN + 1];
__device__ int g_cur[NN];
__device__ int g_bsum[NBLK + 32];
__device__ int g_boff[NBLK + 32];
__device__ int g_is64;

__device__ __forceinline__ float elu1(float v) { return v > 0.f ? v : expm1f(v); }

// ---------------- dtype detection (warp-parallel) ----------------
__global__ void detect_dtype(const int* __restrict__ ei_words) {
    int lane = threadIdx.x & 31;
    int nonzero = 0;
#pragma unroll
    for (int it = 0; it < 32; it++) {
        int i = 1 + 2 * (lane + it * 32);        // odd words of first 2048
        nonzero |= (ei_words[i] != 0);
    }
    unsigned any = __ballot_sync(0xffffffffu, nonzero);
    if (lane == 0) g_is64 = (any == 0u);
}

__global__ void zero_cnt() {
    int i = blockIdx.x * blockDim.x + threadIdx.x;
    if (i < NN) g_cnt[i] = 0;
}

__device__ __forceinline__ int parse_dst(const int* ei, int e) {
    int d = g_is64 ? ei[2 * (EE + e)] : ei[EE + e];
    return min(max(d, 0), NN - 1);
}
__device__ __forceinline__ int parse_src(const int* ei, int e) {
    int s = g_is64 ? ei[2 * e] : ei[e];
    return min(max(s, 0), NN - 1);
}

// ---------------- histogram of dst ----------------
__global__ void edge_hist(const int* __restrict__ ei) {
    int e = blockIdx.x * blockDim.x + threadIdx.x;
    if (e >= EE) return;
    atomicAdd(&g_cnt[parse_dst(ei, e)], 1);
}

// ---------------- multi-block exclusive scan of g_cnt -> rowptr/cur ----------------
__global__ void scan_reduce() {
    int i = blockIdx.x * blockDim.x + threadIdx.x;
    int v = (i < NN) ? g_cnt[i] : 0;
#pragma unroll
    for (int o = 16; o; o >>= 1) v += __shfl_xor_sync(0xffffffffu, v, o);
    __shared__ int sm[8];
    if ((threadIdx.x & 31) == 0) sm[threadIdx.x >> 5] = v;
    __syncthreads();
    if (threadIdx.x == 0) {
        int t = 0;
#pragma unroll
        for (int w = 0; w < 8; w++) t += sm[w];
        g_bsum[blockIdx.x] = t;
    }
}

__global__ void scan_partials() {
    int t = threadIdx.x;
    int v = (t < NBLK) ? g_bsum[t] : 0;
    __shared__ int sm[256];
    sm[t] = v; __syncthreads();
    int acc = v;
#pragma unroll
    for (int o = 1; o < 256; o <<= 1) {
        int add = (t >= o) ? sm[t - o] : 0;
        __syncthreads();
        acc += add; sm[t] = acc;
        __syncthreads();
    }
    if (t < NBLK) g_boff[t] = acc - v;
}

__global__ void scan_apply() {
    int t = threadIdx.x;
    int i = blockIdx.x * 256 + t;
    int v = (i < NN) ? g_cnt[i] : 0;
    __shared__ int sm[256];
    sm[t] = v; __syncthreads();
    int acc = v;
#pragma unroll
    for (int o = 1; o < 256; o <<= 1) {
        int add = (t >= o) ? sm[t - o] : 0;
        __syncthreads();
        acc += add; sm[t] = acc;
        __syncthreads();
    }
    int off = g_boff[blockIdx.x];
    if (i < NN) {
        g_rowptr[i + 1] = off + acc;
        g_cur[i]        = off + acc - v;
    }
    if (i == 0) g_rowptr[0] = 0;
}

// ---------------- scatter edges into CSR ----------------
__global__ void scatter_edges(const int* __restrict__ ei, const float* __restrict__ w) {
    int e = blockIdx.x * blockDim.x + threadIdx.x;
    if (e >= EE) return;
    int d = parse_dst(ei, e);
    int pos = atomicAdd(&g_cur[d], 1);
    g_csr_src[pos] = parse_src(ei, e);
    float wc = fminf(w[e], 4.f);
    g_csr_gate[pos] = fminf(fmaxf(1.f - 0.25f * wc, 0.f), 1.f);
}

// ---------------- fused residual MLP: relu(x@rW1+rb1)@rW2+rb2 -> g_xres ----------------
__global__ void gemm_res_fused(const float* __restrict__ X, const float* __restrict__ W1,
                               const float* __restrict__ B1, const float* __restrict__ W2,
                               const float* __restrict__ B2) {
    int warp = (blockIdx.x * blockDim.x + threadIdx.x) >> 5;
    int r0 = warp * 4;
    if (r0 >= NN) return;
    int lane = threadIdx.x & 31;
    float2 xa[4], t[4];
    float a0[4] = {0,0,0,0}, a1[4] = {0,0,0,0};
#pragma unroll
    for (int r = 0; r < 4; r++) xa[r] = ((const float2*)(X + (size_t)(r0 + r) * 64))[lane];
#pragma unroll
    for (int k = 0; k < 64; k += 2) {
        float2 w0 = ((const float2*)(W1 + k * 64))[lane];
        float2 w1 = ((const float2*)(W1 + (k + 1) * 64))[lane];
#pragma unroll
        for (int r = 0; r < 4; r++) {
            float x0 = __shfl_sync(0xffffffffu, xa[r].x, k >> 1);
            float x1 = __shfl_sync(0xffffffffu, xa[r].y, k >> 1);
            a0[r] += x0 * w0.x + x1 * w1.x;
            a1[r] += x0 * w0.y + x1 * w1.y;
        }
    }
    float bb0 = B1[2 * lane], bb1 = B1[2 * lane + 1];
#pragma unroll
    for (int r = 0; r < 4; r++) {
        t[r].x = fmaxf(a0[r] + bb0, 0.f);
        t[r].y = fmaxf(a1[r] + bb1, 0.f);
        a0[r] = 0.f; a1[r] = 0.f;
    }
#pragma unroll
    for (int k = 0; k < 64; k += 2) {
        float2 w0 = ((const float2*)(W2 + k * 64))[lane];
        float2 w1 = ((const float2*)(W2 + (k + 1) * 64))[lane];
#pragma unroll
        for (int r = 0; r < 4; r++) {
            float x0 = __shfl_sync(0xffffffffu, t[r].x, k >> 1);
            float x1 = __shfl_sync(0xffffffffu, t[r].y, k >> 1);
            a0[r] += x0 * w0.x + x1 * w1.x;
            a1[r] += x0 * w0.y + x1 * w1.y;
        }
    }
    float c0 = B2[2 * lane], c1 = B2[2 * lane + 1];
#pragma unroll
    for (int r = 0; r < 4; r++)
        ((float2*)(g_xres + (size_t)(r0 + r) * 64))[lane] = make_float2(a0[r] + c0, a1[r] + c1);
}

// ---------------- node prep: H=X@W (fp16 out), ad/as, xhat (fp16 out) ----------------
template <int LAYER>
__global__ void node_prep(const float* __restrict__ Xin, const float* __restrict__ W,
                          const float* __restrict__ att) {
    int warp = (blockIdx.x * blockDim.x + threadIdx.x) >> 5;
    int r0 = warp * 4;
    if (r0 >= NN) return;
    int lane = threadIdx.x & 31;
    const float* X = (LAYER == 0) ? Xin : g_h0;
    float2 xa[4];
    float a0[4] = {0,0,0,0}, a1[4] = {0,0,0,0};
#pragma unroll
    for (int r = 0; r < 4; r++) xa[r] = ((const float2*)(X + (size_t)(r0 + r) * 64))[lane];
#pragma unroll
    for (int k = 0; k < 64; k += 2) {
        float2 w0 = ((const float2*)(W + k * 64))[lane];
        float2 w1 = ((const float2*)(W + (k + 1) * 64))[lane];
#pragma unroll
        for (int r = 0; r < 4; r++) {
            float x0 = __shfl_sync(0xffffffffu, xa[r].x, k >> 1);
            float x1 = __shfl_sync(0xffffffffu, xa[r].y, k >> 1);
            a0[r] += x0 * w0.x + x1 * w1.x;
            a1[r] += x0 * w0.y + x1 * w1.y;
        }
    }
    float at0 = att[2 * lane], at1 = att[2 * lane + 1];
    float at2 = att[64 + 2 * lane], at3 = att[65 + 2 * lane];
#pragma unroll
    for (int r = 0; r < 4; r++) {
        ((__half2*)(g_Hh + (size_t)(r0 + r) * 64))[lane] = __floats2half2_rn(a0[r], a1[r]);
        float pa = a0[r] * at0 + a1[r] * at1;
        float pb = a0[r] * at2 + a1[r] * at3;
        float pn = xa[r].x * xa[r].x + xa[r].y * xa[r].y;
#pragma unroll
        for (int o = 16; o; o >>= 1) {
            pa += __shfl_xor_sync(0xffffffffu, pa, o);
            pb += __shfl_xor_sync(0xffffffffu, pb, o);
            pn += __shfl_xor_sync(0xffffffffu, pn, o);
        }
        float inv = 1.f / fmaxf(sqrtf(pn), 1e-8f);
        ((__half2*)(g_xh + (size_t)(r0 + r) * 64))[lane] =
            __floats2half2_rn(xa[r].x * inv, xa[r].y * inv);
        if (lane == 0) { g_ad[r0 + r] = pa; g_as[r0 + r] = pb; }
    }
}

// unpack 8 halves (loaded as float4) to 8 floats
__device__ __forceinline__ void h8_to_f8(float4 raw, float* f) {
    const __half2* h = (const __half2*)&raw;
#pragma unroll
    for (int i = 0; i < 4; i++) {
        float2 v = __half22float2(h[i]);
        f[2 * i] = v.x; f[2 * i + 1] = v.y;
    }
}

// ---------------- fused edge engine: warp per node, no atomics ----------------
// 8 lanes/edge, each lane covers 8 columns via one 16B fp16 load.
template <int LAYER>
__global__ void edge_fused(const float* __restrict__ beta, const float* __restrict__ B,
                           float* __restrict__ outp) {
    int n = (blockIdx.x * blockDim.x + threadIdx.x) >> 5;
    if (n >= NN) return;
    int lane = threadIdx.x & 31;
    int p = lane & 7;          // column-slot within 8-lane group (8 cols each)
    int grp = lane >> 3;       // edge group 0..3

    float xq[8];
    h8_to_f8(((const float4*)(g_xh + (size_t)n * 64))[p], xq);
    float ad = g_ad[n];
    int beg = g_rowptr[n], end = g_rowptr[n + 1];
    float bb = 1.f / (1.f + __expf(-beta[0]));

    const float NINF = __int_as_float(0xff800000);
    float m = NINF, sg = 0.f, sc = 0.f;

    for (int j0 = beg; j0 < end; j0 += 4) {
        int idx = j0 + grp;
        int s = (idx < end) ? g_csr_src[idx] : 0;
        float q[8];
        h8_to_f8(((const float4*)(g_xh + (size_t)s * 64))[p], q);
        float d = 0.f;
#pragma unroll
        for (int i = 0; i < 8; i++) d += xq[i] * q[i];
        d += __shfl_xor_sync(0xffffffffu, d, 4, 8);
        d += __shfl_xor_sync(0xffffffffu, d, 2, 8);
        d += __shfl_xor_sync(0xffffffffu, d, 1, 8);
        float dsel = __shfl_sync(0xffffffffu, d, (lane * 8) & 31);
        int   ssel = __shfl_sync(0xffffffffu, s, (lane * 8) & 31);
        int cnt = min(4, end - j0);
        if (lane < cnt) {
            float lg = ad + g_as[ssel];
            lg = fmaxf(lg, 0.2f * lg);                   // leaky relu
            float ecv = __expf(dsel);                    // cos in [-1,1]: no shift
            g_ec[j0 + lane] = make_float2(lg, ecv);
            float mo = m;
            m = fmaxf(m, lg);
            sg = sg * __expf(mo - m) + __expf(lg - m);   // online softmax
            sc += ecv;
        }
    }
#pragma unroll
    for (int o = 1; o <= 2; o <<= 1) {
        float m2  = __shfl_xor_sync(0xffffffffu, m, o, 4);
        float sg2 = __shfl_xor_sync(0xffffffffu, sg, o, 4);
        float sc2 = __shfl_xor_sync(0xffffffffu, sc, o, 4);
        float mm = fmaxf(m, m2);
        float t1 = (sg  > 0.f) ? sg  * __expf(m  - mm) : 0.f;
        float t2 = (sg2 > 0.f) ? sg2 * __expf(m2 - mm) : 0.f;
        m = mm; sg = t1 + t2; sc += sc2;
    }
    m  = __shfl_sync(0xffffffffu, m, 0);
    sg = __shfl_sync(0xffffffffu, sg, 0);
    sc = __shfl_sync(0xffffffffu, sc, 0);
    float wg = (1.f - bb) / (sg + 1e-16f);
    float wc = bb / (sc + 1e-16f);

    // Pass C: fused alpha, gate, exp; unnormalized aggregate; divide at end
    float acc[8] = {0,0,0,0,0,0,0,0};
    float st = 0.f;
    for (int j0 = beg; j0 < end; j0 += 4) {
        int idx = j0 + grp;
        int s = (idx < end) ? g_csr_src[idx] : 0;
        int cnt = min(4, end - j0);
        float et = 0.f;
        if (lane < cnt) {
            float2 le = g_ec[j0 + lane];
            float eg = __expf(le.x - m);
            float tv = (eg * wg + le.y * wc) * g_csr_gate[j0 + lane];  // in [0,1]
            et = __expf(tv);
            st += et;
        }
        float etg = __shfl_sync(0xffffffffu, et, grp);
        float h[8];
        h8_to_f8(((const float4*)(g_Hh + (size_t)s * 64))[p], h);
#pragma unroll
        for (int i = 0; i < 8; i++) acc[i] += etg * h[i];
    }
    st += __shfl_xor_sync(0xffffffffu, st, 1, 4);
    st += __shfl_xor_sync(0xffffffffu, st, 2, 4);
    st  = __shfl_sync(0xffffffffu, st, 0);
#pragma unroll
    for (int i = 0; i < 8; i++) {
        acc[i] += __shfl_xor_sync(0xffffffffu, acc[i], 8);
        acc[i] += __shfl_xor_sync(0xffffffffu, acc[i], 16);
    }
    float inv = 1.f / (st + 1e-16f);
    if (lane < 8) {                                  // grp==0 lanes hold final cols 8p..8p+8
        float o[8];
#pragma unroll
        for (int i = 0; i < 8; i++) o[i] = acc[i] * inv + B[p * 8 + i];
        if (LAYER == 0) {
#pragma unroll
            for (int i = 0; i < 8; i++) o[i] = elu1(elu1(o[i]));
            float4* dst = (float4*)(g_h0 + (size_t)n * 64 + p * 8);
            dst[0] = make_float4(o[0], o[1], o[2], o[3]);
            dst[1] = make_float4(o[4], o[5], o[6], o[7]);
        } else {
            const float4* rr = (const float4*)(g_xres + (size_t)n * 64 + p * 8);
            float4 r0 = rr[0], r1 = rr[1];
            o[0] = elu1(o[0]) + r0.x; o[1] = elu1(o[1]) + r0.y;
            o[2] = elu1(o[2]) + r0.z; o[3] = elu1(o[3]) + r0.w;
            o[4] = elu1(o[4]) + r1.x; o[5] = elu1(o[5]) + r1.y;
            o[6] = elu1(o[6]) + r1.z; o[7] = elu1(o[7]) + r1.w;
            float4* dst = (float4*)(outp + (size_t)n * 64 + p * 8);
            dst[0] = make_float4(o[0], o[1], o[2], o[3]);
            dst[1] = make_float4(o[4], o[5], o[6], o[7]);
        }
    }
}

// ---------------- launch ----------------
extern "C" void kernel_launch(void* const* d_in, const int* in_sizes, int n_in,
                              void* d_out, int out_size) {
    const float* x     = (const float*)d_in[0];
    const int*   ei    = (const int*)d_in[1];
    const float* ea    = (const float*)d_in[2];
    const float* W0    = (const float*)d_in[3];
    const float* att0  = (const float*)d_in[4];
    const float* beta0 = (const float*)d_in[5];
    const float* b0    = (const float*)d_in[6];
    const float* W1    = (const float*)d_in[7];
    const float* att1  = (const float*)d_in[8];
    const float* beta1 = (const float*)d_in[9];
    const float* b1    = (const float*)d_in[10];
    const float* rW1   = (const float*)d_in[11];
    const float* rb1   = (const float*)d_in[12];
    const float* rW2   = (const float*)d_in[13];
    const float* rb2   = (const float*)d_in[14];
    float* out = (float*)d_out;

    const int EDGE_GRID  = EE / 256;                 // 5000
    const int PREP_GRID  = (NN / 4 + 7) / 8;         // 1563 (4 rows/warp, 8 warps/blk)
    const int EDGEF_GRID = NN / 8;                   // 6250 (warp per node)

    detect_dtype<<<1, 32>>>(ei);
    zero_cnt<<<NBLK, 256>>>();
    edge_hist<<<EDGE_GRID, 256>>>(ei);
    scan_reduce<<<NBLK, 256>>>();
    scan_partials<<<1, 256>>>();
    scan_apply<<<NBLK, 256>>>();
    scatter_edges<<<EDGE_GRID, 256>>>(ei, ea);

    gemm_res_fused<<<PREP_GRID, 256>>>(x, rW1, rb1, rW2, rb2);

    node_prep<0><<<PREP_GRID, 256>>>(x, W0, att0);
    edge_fused<0><<<EDGEF_GRID, 256>>>(beta0, b0, out);

    node_prep<1><<<PREP_GRID, 256>>>(x, W1, att1);
    edge_fused<1><<<EDGEF_GRID, 256>>>(beta1, b1, out);
}

// round 15
// speedup vs baseline: 1.8082x; 1.0081x over previous
#include <cuda_runtime.h>
#include <cuda_fp16.h>
#include <math.h>

#define NN 50000
#define EE 1280000
#define NBLK 196            // ceil(NN/256)

// ---------------- device scratch ----------------
__device__ __align__(16) int    g_csr_src[EE];
__device__ __align__(16) float  g_csr_gate[EE];
__device__ __align__(16) float2 g_ec[EE + 8];       // (exp(logit), exp(cos)) per CSR edge
__device__ __align__(16) __half g_Hh[NN * 64];      // H = X@W   (fp16 for gather BW)
__device__ __align__(16) __half g_xh[NN * 64];      // xhat      (fp16 for gather BW)
__device__ __align__(16) float  g_h0[NN * 64];
__device__ __align__(16) float  g_xres[NN * 64];
__device__ __align__(16) float  g_ad[NN];
__device__ __align__(16) float  g_as[NN];
__device__ int g_cnt[NN];
__device__ int g_rowptr[NN + 1];
__device__ int g_cur[NN];
__device__ int g_bsum[NBLK + 32];
__device__ int g_boff[NBLK + 32];
__device__ int g_is64;

__device__ __forceinline__ float elu1(float v) { return v > 0.f ? v : expm1f(v); }

// ---------------- dtype detection (warp-parallel) ----------------
__global__ void detect_dtype(const int* __restrict__ ei_words) {
    int lane = threadIdx.x & 31;
    int nonzero = 0;
#pragma unroll
    for (int it = 0; it < 32; it++) {
        int i = 1 + 2 * (lane + it * 32);        // odd words of first 2048
        nonzero |= (ei_words[i] != 0);
    }
    unsigned any = __ballot_sync(0xffffffffu, nonzero);
    if (lane == 0) g_is64 = (any == 0u);
}

__global__ void zero_cnt() {
    int i = blockIdx.x * blockDim.x + threadIdx.x;
    if (i < NN) g_cnt[i] = 0;
}

__device__ __forceinline__ int parse_dst(const int* ei, int e) {
    int d = g_is64 ? ei[2 * (EE + e)] : ei[EE + e];
    return min(max(d, 0), NN - 1);
}
__device__ __forceinline__ int parse_src(const int* ei, int e) {
    int s = g_is64 ? ei[2 * e] : ei[e];
    return min(max(s, 0), NN - 1);
}

// ---------------- histogram of dst ----------------
__global__ void edge_hist(const int* __restrict__ ei) {
    int e = blockIdx.x * blockDim.x + threadIdx.x;
    if (e >= EE) return;
    atomicAdd(&g_cnt[parse_dst(ei, e)], 1);
}

// ---------------- multi-block exclusive scan of g_cnt -> rowptr/cur ----------------
__global__ void scan_reduce() {
    int i = blockIdx.x * blockDim.x + threadIdx.x;
    int v = (i < NN) ? g_cnt[i] : 0;
#pragma unroll
    for (int o = 16; o; o >>= 1) v += __shfl_xor_sync(0xffffffffu, v, o);
    __shared__ int sm[8];
    if ((threadIdx.x & 31) == 0) sm[threadIdx.x >> 5] = v;
    __syncthreads();
    if (threadIdx.x == 0) {
        int t = 0;
#pragma unroll
        for (int w = 0; w < 8; w++) t += sm[w];
        g_bsum[blockIdx.x] = t;
    }
}

__global__ void scan_partials() {
    int t = threadIdx.x;
    int v = (t < NBLK) ? g_bsum[t] : 0;
    __shared__ int sm[256];
    sm[t] = v; __syncthreads();
    int acc = v;
#pragma unroll
    for (int o = 1; o < 256; o <<= 1) {
        int add = (t >= o) ? sm[t - o] : 0;
        __syncthreads();
        acc += add; sm[t] = acc;
        __syncthreads();
    }
    if (t < NBLK) g_boff[t] = acc - v;
}

__global__ void scan_apply() {
    int t = threadIdx.x;
    int i = blockIdx.x * 256 + t;
    int v = (i < NN) ? g_cnt[i] : 0;
    __shared__ int sm[256];
    sm[t] = v; __syncthreads();
    int acc = v;
#pragma unroll
    for (int o = 1; o < 256; o <<= 1) {
        int add = (t >= o) ? sm[t - o] : 0;
        __syncthreads();
        acc += add; sm[t] = acc;
        __syncthreads();
    }
    int off = g_boff[blockIdx.x];
    if (i < NN) {
        g_rowptr[i + 1] = off + acc;
        g_cur[i]        = off + acc - v;
    }
    if (i == 0) g_rowptr[0] = 0;
}

// ---------------- scatter edges into CSR ----------------
__global__ void scatter_edges(const int* __restrict__ ei, const float* __restrict__ w) {
    int e = blockIdx.x * blockDim.x + threadIdx.x;
    if (e >= EE) return;
    int d = parse_dst(ei, e);
    int pos = atomicAdd(&g_cur[d], 1);
    g_csr_src[pos] = parse_src(ei, e);
    float wc = fminf(w[e], 4.f);
    g_csr_gate[pos] = fminf(fmaxf(1.f - 0.25f * wc, 0.f), 1.f);
}

// ---------------- fused residual MLP: relu(x@rW1+rb1)@rW2+rb2 -> g_xres ----------------
__global__ void gemm_res_fused(const float* __restrict__ X, const float* __restrict__ W1,
                               const float* __restrict__ B1, const float* __restrict__ W2,
                               const float* __restrict__ B2) {
    int warp = (blockIdx.x * blockDim.x + threadIdx.x) >> 5;
    int r0 = warp * 4;
    if (r0 >= NN) return;
    int lane = threadIdx.x & 31;
    float2 xa[4], t[4];
    float a0[4] = {0,0,0,0}, a1[4] = {0,0,0,0};
#pragma unroll
    for (int r = 0; r < 4; r++) xa[r] = ((const float2*)(X + (size_t)(r0 + r) * 64))[lane];
#pragma unroll
    for (int k = 0; k < 64; k += 2) {
        float2 w0 = ((const float2*)(W1 + k * 64))[lane];
        float2 w1 = ((const float2*)(W1 + (k + 1) * 64))[lane];
#pragma unroll
        for (int r = 0; r < 4; r++) {
            float x0 = __shfl_sync(0xffffffffu, xa[r].x, k >> 1);
            float x1 = __shfl_sync(0xffffffffu, xa[r].y, k >> 1);
            a0[r] += x0 * w0.x + x1 * w1.x;
            a1[r] += x0 * w0.y + x1 * w1.y;
        }
    }
    float bb0 = B1[2 * lane], bb1 = B1[2 * lane + 1];
#pragma unroll
    for (int r = 0; r < 4; r++) {
        t[r].x = fmaxf(a0[r] + bb0, 0.f);
        t[r].y = fmaxf(a1[r] + bb1, 0.f);
        a0[r] = 0.f; a1[r] = 0.f;
    }
#pragma unroll
    for (int k = 0; k < 64; k += 2) {
        float2 w0 = ((const float2*)(W2 + k * 64))[lane];
        float2 w1 = ((const float2*)(W2 + (k + 1) * 64))[lane];
#pragma unroll
        for (int r = 0; r < 4; r++) {
            float x0 = __shfl_sync(0xffffffffu, t[r].x, k >> 1);
            float x1 = __shfl_sync(0xffffffffu, t[r].y, k >> 1);
            a0[r] += x0 * w0.x + x1 * w1.x;
            a1[r] += x0 * w0.y + x1 * w1.y;
        }
    }
    float c0 = B2[2 * lane], c1 = B2[2 * lane + 1];
#pragma unroll
    for (int r = 0; r < 4; r++)
        ((float2*)(g_xres + (size_t)(r0 + r) * 64))[lane] = make_float2(a0[r] + c0, a1[r] + c1);
}

// ---------------- node prep: H=X@W (fp16 out), ad/as, xhat (fp16 out) ----------------
template <int LAYER>
__global__ void node_prep(const float* __restrict__ Xin, const float* __restrict__ W,
                          const float* __restrict__ att) {
    int warp = (blockIdx.x * blockDim.x + threadIdx.x) >> 5;
    int r0 = warp * 4;
    if (r0 >= NN) return;
    int lane = threadIdx.x & 31;
    const float* X = (LAYER == 0) ? Xin : g_h0;
    float2 xa[4];
    float a0[4] = {0,0,0,0}, a1[4] = {0,0,0,0};
#pragma unroll
    for (int r = 0; r < 4; r++) xa[r] = ((const float2*)(X + (size_t)(r0 + r) * 64))[lane];
#pragma unroll
    for (int k = 0; k < 64; k += 2) {
        float2 w0 = ((const float2*)(W + k * 64))[lane];
        float2 w1 = ((const float2*)(W + (k + 1) * 64))[lane];
#pragma unroll
        for (int r = 0; r < 4; r++) {
            float x0 = __shfl_sync(0xffffffffu, xa[r].x, k >> 1);
            float x1 = __shfl_sync(0xffffffffu, xa[r].y, k >> 1);
            a0[r] += x0 * w0.x + x1 * w1.x;
            a1[r] += x0 * w0.y + x1 * w1.y;
        }
    }
    float at0 = att[2 * lane], at1 = att[2 * lane + 1];
    float at2 = att[64 + 2 * lane], at3 = att[65 + 2 * lane];
#pragma unroll
    for (int r = 0; r < 4; r++) {
        ((__half2*)(g_Hh + (size_t)(r0 + r) * 64))[lane] = __floats2half2_rn(a0[r], a1[r]);
        float pa = a0[r] * at0 + a1[r] * at1;
        float pb = a0[r] * at2 + a1[r] * at3;
        float pn = xa[r].x * xa[r].x + xa[r].y * xa[r].y;
#pragma unroll
        for (int o = 16; o; o >>= 1) {
            pa += __shfl_xor_sync(0xffffffffu, pa, o);
            pb += __shfl_xor_sync(0xffffffffu, pb, o);
            pn += __shfl_xor_sync(0xffffffffu, pn, o);
        }
        float inv = 1.f / fmaxf(sqrtf(pn), 1e-8f);
        ((__half2*)(g_xh + (size_t)(r0 + r) * 64))[lane] =
            __floats2half2_rn(xa[r].x * inv, xa[r].y * inv);
        if (lane == 0) { g_ad[r0 + r] = pa; g_as[r0 + r] = pb; }
    }
}

// unpack 8 halves (loaded as float4) to 8 floats
__device__ __forceinline__ void h8_to_f8(float4 raw, float* f) {
    const __half2* h = (const __half2*)&raw;
#pragma unroll
    for (int i = 0; i < 4; i++) {
        float2 v = __half22float2(h[i]);
        f[2 * i] = v.x; f[2 * i + 1] = v.y;
    }
}

// ---------------- fused edge engine: warp per node, no atomics, no max-shift ----------------
// 8 lanes/edge, each lane covers 8 columns via one 16B fp16 load.
// Softmax shift-invariance: logits bounded (|lg| ~< 20 << 88), so raw exp is safe.
// Both loops software-pipelined: next iteration's index + gather issued before compute.
template <int LAYER>
__global__ void edge_fused(const float* __restrict__ beta, const float* __restrict__ B,
                           float* __restrict__ outp) {
    int n = (blockIdx.x * blockDim.x + threadIdx.x) >> 5;
    if (n >= NN) return;
    int lane = threadIdx.x & 31;
    int p = lane & 7;          // column-slot within 8-lane group (8 cols each)
    int grp = lane >> 3;       // edge group 0..3
    int esel = (lane * 8) & 31;

    float xq[8];
    h8_to_f8(((const float4*)(g_xh + (size_t)n * 64))[p], xq);
    float ad = g_ad[n];
    int beg = g_rowptr[n], end = g_rowptr[n + 1];
    float bb = 1.f / (1.f + __expf(-beta[0]));

    float sg = 0.f, sc = 0.f;

    // ---- pass A: dot + logit, raw exps, sums (pipelined) ----
    {
        int idx = beg + grp;
        int s = (idx < end) ? g_csr_src[idx] : 0;
        float4 raw = ((const float4*)(g_xh + (size_t)s * 64))[p];
        for (int j0 = beg; j0 < end; j0 += 4) {
            int idxn = j0 + 4 + grp;
            int sn = (idxn < end) ? g_csr_src[idxn] : 0;
            float4 rawn = ((const float4*)(g_xh + (size_t)sn * 64))[p];
            float q[8];
            h8_to_f8(raw, q);
            float d = 0.f;
#pragma unroll
            for (int i = 0; i < 8; i++) d += xq[i] * q[i];
            d += __shfl_xor_sync(0xffffffffu, d, 4, 8);
            d += __shfl_xor_sync(0xffffffffu, d, 2, 8);
            d += __shfl_xor_sync(0xffffffffu, d, 1, 8);
            float dsel = __shfl_sync(0xffffffffu, d, esel);
            int   ssel = __shfl_sync(0xffffffffu, s, esel);
            if (lane < min(4, end - j0)) {
                float lg = ad + g_as[ssel];
                lg = fmaxf(lg, 0.2f * lg);               // leaky relu
                float eg = __expf(lg);                   // no shift: |lg| small
                float ec = __expf(dsel);                 // cos in [-1,1]
                g_ec[j0 + lane] = make_float2(eg, ec);
                sg += eg; sc += ec;
            }
            s = sn; raw = rawn;
        }
    }
    sg += __shfl_xor_sync(0xffffffffu, sg, 1, 4);
    sg += __shfl_xor_sync(0xffffffffu, sg, 2, 4);
    sc += __shfl_xor_sync(0xffffffffu, sc, 1, 4);
    sc += __shfl_xor_sync(0xffffffffu, sc, 2, 4);
    sg = __shfl_sync(0xffffffffu, sg, 0);
    sc = __shfl_sync(0xffffffffu, sc, 0);
    float wg = (1.f - bb) / (sg + 1e-16f);
    float wc = bb / (sc + 1e-16f);

    // ---- pass C: fused alpha, gate, exp; unnormalized aggregate (pipelined) ----
    float acc[8] = {0,0,0,0,0,0,0,0};
    float st = 0.f;
    {
        int idx = beg + grp;
        int s = (idx < end) ? g_csr_src[idx] : 0;
        float4 hraw = ((const float4*)(g_Hh + (size_t)s * 64))[p];
        int eidx = min(beg + lane, end - 1);
        float2 le = g_ec[eidx];
        float gt = g_csr_gate[eidx];
        for (int j0 = beg; j0 < end; j0 += 4) {
            int idxn = j0 + 4 + grp;
            int sn = (idxn < end) ? g_csr_src[idxn] : 0;
            float4 hrawn = ((const float4*)(g_Hh + (size_t)sn * 64))[p];
            int eidxn = min(j0 + 4 + lane, end - 1);
            float2 len = g_ec[eidxn];
            float gtn = g_csr_gate[eidxn];

            float et = 0.f;
            if (lane < min(4, end - j0)) {
                float tv = (le.x * wg + le.y * wc) * gt;   // in [0,1]
                et = __expf(tv);
                st += et;
            }
            float etg = __shfl_sync(0xffffffffu, et, grp);
            float h[8];
            h8_to_f8(hraw, h);
#pragma unroll
            for (int i = 0; i < 8; i++) acc[i] += etg * h[i];

            s = sn; hraw = hrawn; le = len; gt = gtn;
        }
    }
    st += __shfl_xor_sync(0xffffffffu, st, 1, 4);
    st += __shfl_xor_sync(0xffffffffu, st, 2, 4);
    st  = __shfl_sync(0xffffffffu, st, 0);
#pragma unroll
    for (int i = 0; i < 8; i++) {
        acc[i] += __shfl_xor_sync(0xffffffffu, acc[i], 8);
        acc[i] += __shfl_xor_sync(0xffffffffu, acc[i], 16);
    }
    float inv = 1.f / (st + 1e-16f);
    if (lane < 8) {                                  // grp==0 lanes hold final cols 8p..8p+8
        float o[8];
#pragma unroll
        for (int i = 0; i < 8; i++) o[i] = acc[i] * inv + B[p * 8 + i];
        if (LAYER == 0) {
#pragma unroll
            for (int i = 0; i < 8; i++) o[i] = elu1(elu1(o[i]));
            float4* dst = (float4*)(g_h0 + (size_t)n * 64 + p * 8);
            dst[0] = make_float4(o[0], o[1], o[2], o[3]);
            dst[1] = make_float4(o[4], o[5], o[6], o[7]);
        } else {
            const float4* rr = (const float4*)(g_xres + (size_t)n * 64 + p * 8);
            float4 r0 = rr[0], r1 = rr[1];
            o[0] = elu1(o[0]) + r0.x; o[1] = elu1(o[1]) + r0.y;
            o[2] = elu1(o[2]) + r0.z; o[3] = elu1(o[3]) + r0.w;
            o[4] = elu1(o[4]) + r1.x; o[5] = elu1(o[5]) + r1.y;
            o[6] = elu1(o[6]) + r1.z; o[7] = elu1(o[7]) + r1.w;
            float4* dst = (float4*)(outp + (size_t)n * 64 + p * 8);
            dst[0] = make_float4(o[0], o[1], o[2], o[3]);
            dst[1] = make_float4(o[4], o[5], o[6], o[7]);
        }
    }
}

// ---------------- launch ----------------
extern "C" void kernel_launch(void* const* d_in, const int* in_sizes, int n_in,
                              void* d_out, int out_size) {
    const float* x     = (const float*)d_in[0];
    const int*   ei    = (const int*)d_in[1];
    const float* ea    = (const float*)d_in[2];
    const float* W0    = (const float*)d_in[3];
    const float* att0  = (const float*)d_in[4];
    const float* beta0 = (const float*)d_in[5];
    const float* b0    = (const float*)d_in[6];
    const float* W1    = (const float*)d_in[7];
    const float* att1  = (const float*)d_in[8];
    const float* beta1 = (const float*)d_in[9];
    const float* b1    = (const float*)d_in[10];
    const float* rW1   = (const float*)d_in[11];
    const float* rb1   = (const float*)d_in[12];
    const float* rW2   = (const float*)d_in[13];
    const float* rb2   = (const float*)d_in[14];
    float* out = (float*)d_out;

    const int EDGE_GRID  = EE / 256;                 // 5000
    const int PREP_GRID  = (NN / 4 + 7) / 8;         // 1563 (4 rows/warp, 8 warps/blk)
    const int EDGEF_GRID = NN / 8;                   // 6250 (warp per node)

    detect_dtype<<<1, 32>>>(ei);
    zero_cnt<<<NBLK, 256>>>();
    edge_hist<<<EDGE_GRID, 256>>>(ei);
    scan_reduce<<<NBLK, 256>>>();
    scan_partials<<<1, 256>>>();
    scan_apply<<<NBLK, 256>>>();
    scatter_edges<<<EDGE_GRID, 256>>>(ei, ea);

    gemm_res_fused<<<PREP_GRID, 256>>>(x, rW1, rb1, rW2, rb2);

    node_prep<0><<<PREP_GRID, 256>>>(x, W0, att0);
    edge_fused<0><<<EDGEF_GRID, 256>>>(beta0, b0, out);

    node_prep<1><<<PREP_GRID, 256>>>(x, W1, att1);
    edge_fused<1><<<EDGEF_GRID, 256>>>(beta1, b1, out);
}